// round 4
// baseline (speedup 1.0000x reference)
#include <cuda_runtime.h>
#include <math.h>

// ---------------------------------------------------------------------------
// Shapes (fixed by the problem)
// ---------------------------------------------------------------------------
#define B    32
#define L    65536
#define LOUT 64536          // L - 1000 (slice [500:-500])

// Scratch (device globals; allocation in kernel_launch is forbidden)
__device__ float g_y[(size_t)B * 40 * L];   // motif output (post-softplus)
__device__ float g_s[(size_t)B * 4 * L];    // reduce output
__device__ float g_t[(size_t)B * 4 * L];    // fftconv output
__device__ float g_m[(size_t)B * 40 * L];   // motifact (gated)

// ---------------------------------------------------------------------------
// f32x2 packed helpers (sm_100a)
// ---------------------------------------------------------------------------
typedef unsigned long long u64;

__device__ __forceinline__ u64 pack2(float lo, float hi) {
    u64 r;
    asm("mov.b64 %0, {%1, %2};" : "=l"(r) : "f"(lo), "f"(hi));
    return r;
}
__device__ __forceinline__ void unpack2(u64 v, float& lo, float& hi) {
    asm("mov.b64 {%0, %1}, %2;" : "=f"(lo), "=f"(hi) : "l"(v));
}
__device__ __forceinline__ u64 ffma2(u64 a, u64 b, u64 c) {
    u64 d;
    asm("fma.rn.f32x2 %0, %1, %2, %3;" : "=l"(d) : "l"(a), "l"(b), "l"(c));
    return d;
}

// ---------------------------------------------------------------------------
// Kernel 1: motif conv (4->40, K=51, pad 25) + softplus + reduce (40->4, 1x1)
//   f32x2: accumulators paired over adjacent output channels.
// ---------------------------------------------------------------------------
#define T1   512            // output positions per block
#define TH1  128
#define K1P  52             // 51 padded to mult of 4 (pad taps have w=0)
#define XW1  564            // T1 + K1P + 4 rounding, mult of 4

__global__ __launch_bounds__(TH1)
void motif_kernel(const float* __restrict__ x,
                  const float* __restrict__ wm, const float* __restrict__ bm,
                  const float* __restrict__ wr, const float* __restrict__ br)
{
    __shared__ __align__(16) float swm[4 * K1P * 40];  // [c][k][oc], k padded
    __shared__ float swr[4 * 40];                      // [rc][oc]
    __shared__ float sbm[40];
    __shared__ float sbr[4];
    __shared__ __align__(16) float sx[4 * XW1];

    const int b   = blockIdx.y;
    const int l0  = blockIdx.x * T1;
    const int tid = threadIdx.x;

    // weights -> smem, transposed to [c][k][oc] with k zero-padded to 52
    for (int i = tid; i < 4 * K1P * 40; i += TH1) {
        int c  = i / (K1P * 40);
        int r  = i - c * (K1P * 40);
        int k  = r / 40;
        int oc = r - k * 40;
        swm[i] = (k < 51) ? wm[(oc * 4 + c) * 51 + k] : 0.f;
    }
    for (int i = tid; i < 160; i += TH1) swr[i] = wr[i];
    if (tid < 40) sbm[tid] = bm[tid];
    if (tid < 4)  sbr[tid] = br[tid];

    // x window [l0-25, l0-25+XW1)
    for (int i = tid; i < 4 * XW1; i += TH1) {
        int c   = i / XW1;
        int off = i - c * XW1;
        int g   = l0 - 25 + off;
        sx[i]   = (g >= 0 && g < L) ? x[(b * 4 + c) * L + g] : 0.f;
    }
    __syncthreads();

    const int tp = tid * 4;     // 4 consecutive output positions per thread

    float sacc[4][4];
#pragma unroll
    for (int rc = 0; rc < 4; rc++) {
        float bv = sbr[rc];
#pragma unroll
        for (int j = 0; j < 4; j++) sacc[rc][j] = bv;
    }

    for (int ocg = 0; ocg < 40; ocg += 8) {
        // packed accumulators: pair p = channels (ocg+2p, ocg+2p+1)
        u64 accP[4][4];
#pragma unroll
        for (int p = 0; p < 4; p++) {
            u64 bv = pack2(sbm[ocg + 2 * p], sbm[ocg + 2 * p + 1]);
#pragma unroll
            for (int j = 0; j < 4; j++) accP[p][j] = bv;
        }

#pragma unroll
        for (int c = 0; c < 4; c++) {
            const float* xb = &sx[c * XW1 + tp];
            const float* wb = &swm[c * (K1P * 40) + ocg];
#pragma unroll 1
            for (int kg = 0; kg < K1P / 4; kg++) {
                const int k0 = kg * 4;
                float xq[8];
                float4 xa = *(const float4*)(xb + k0);
                float4 xc = *(const float4*)(xb + k0 + 4);
                xq[0]=xa.x; xq[1]=xa.y; xq[2]=xa.z; xq[3]=xa.w;
                xq[4]=xc.x; xq[5]=xc.y; xq[6]=xc.z; xq[7]=xc.w;
#pragma unroll
                for (int kk = 0; kk < 4; kk++) {
                    ulonglong2 wp0 = *(const ulonglong2*)(wb + (k0 + kk) * 40);
                    ulonglong2 wp1 = *(const ulonglong2*)(wb + (k0 + kk) * 40 + 4);
#pragma unroll
                    for (int j = 0; j < 4; j++) {
                        u64 xd = pack2(xq[kk + j], xq[kk + j]);
                        accP[0][j] = ffma2(wp0.x, xd, accP[0][j]);
                        accP[1][j] = ffma2(wp0.y, xd, accP[1][j]);
                        accP[2][j] = ffma2(wp1.x, xd, accP[2][j]);
                        accP[3][j] = ffma2(wp1.y, xd, accP[3][j]);
                    }
                }
            }
        }

        // softplus, write y, accumulate reduce
#pragma unroll
        for (int p = 0; p < 4; p++) {
#pragma unroll
            for (int e = 0; e < 2; e++) {
                const int oc = ocg + 2 * p + e;
                float4 yv;
                float* yp = (float*)&yv;
#pragma unroll
                for (int j = 0; j < 4; j++) {
                    float v0, v1;
                    unpack2(accP[p][j], v0, v1);
                    float v = e ? v1 : v0;
                    float sp = fmaxf(v, 0.f) + __logf(1.f + __expf(-fabsf(v)));
                    yp[j] = sp;
#pragma unroll
                    for (int rc = 0; rc < 4; rc++)
                        sacc[rc][j] = fmaf(swr[rc * 40 + oc], sp, sacc[rc][j]);
                }
                *(float4*)&g_y[(size_t)(b * 40 + oc) * L + l0 + tp] = yv;
            }
        }
    }

#pragma unroll
    for (int rc = 0; rc < 4; rc++) {
        float4 sv = make_float4(sacc[rc][0], sacc[rc][1], sacc[rc][2], sacc[rc][3]);
        *(float4*)&g_s[(size_t)(b * 4 + rc) * L + l0 + tp] = sv;
    }
}

// ---------------------------------------------------------------------------
// Kernel 2: fftconv (4->4, K=401, pad 200)
//   f32x2: accumulators paired over output channels (oc0,oc1) / (oc2,oc3).
//   Weight pairs come straight out of the existing [c][k][4] smem layout
//   via ld.shared.v2.u64 — no pack instructions for weights.
// ---------------------------------------------------------------------------
#define T3   512
#define TH3  128
#define K3P  404            // 401 padded to mult of 4
#define XW3  920            // T3 + K3P + 4, mult of 4

__global__ __launch_bounds__(TH3)
void fftconv_kernel(const float* __restrict__ wf, const float* __restrict__ bf)
{
    __shared__ __align__(16) float sw[4 * K3P * 4];    // [c][k][oc]
    __shared__ float sb[4];
    __shared__ __align__(16) float ss[4 * XW3];

    const int b   = blockIdx.y;
    const int l0  = blockIdx.x * T3;
    const int tid = threadIdx.x;

    for (int i = tid; i < 4 * K3P * 4; i += TH3) {
        int c  = i / (K3P * 4);
        int r  = i - c * (K3P * 4);
        int k  = r / 4;
        int oc = r - k * 4;
        sw[i] = (k < 401) ? wf[(oc * 4 + c) * 401 + k] : 0.f;
    }
    if (tid < 4) sb[tid] = bf[tid];

    for (int i = tid; i < 4 * XW3; i += TH3) {
        int c   = i / XW3;
        int off = i - c * XW3;
        int g   = l0 - 200 + off;
        ss[i]   = (g >= 0 && g < L) ? g_s[(size_t)(b * 4 + c) * L + g] : 0.f;
    }
    __syncthreads();

    const int tp = tid * 4;
    u64 accA[4], accB[4];   // accA[j] = (oc0, oc1) @ pos j; accB[j] = (oc2, oc3)
    {
        u64 iA = pack2(sb[0], sb[1]);
        u64 iB = pack2(sb[2], sb[3]);
#pragma unroll
        for (int j = 0; j < 4; j++) { accA[j] = iA; accB[j] = iB; }
    }

#pragma unroll
    for (int c = 0; c < 4; c++) {
        const float* xb = &ss[c * XW3 + tp];
        const float* wb = &sw[c * (K3P * 4)];
#pragma unroll 1
        for (int kg = 0; kg < K3P / 4; kg++) {
            const int k0 = kg * 4;
            float xq[8];
            float4 xa = *(const float4*)(xb + k0);
            float4 xc = *(const float4*)(xb + k0 + 4);
            xq[0]=xa.x; xq[1]=xa.y; xq[2]=xa.z; xq[3]=xa.w;
            xq[4]=xc.x; xq[5]=xc.y; xq[6]=xc.z; xq[7]=xc.w;
#pragma unroll
            for (int kk = 0; kk < 4; kk++) {
                ulonglong2 wv = *(const ulonglong2*)(wb + (k0 + kk) * 4);
#pragma unroll
                for (int j = 0; j < 4; j++) {
                    u64 xd = pack2(xq[kk + j], xq[kk + j]);
                    accA[j] = ffma2(wv.x, xd, accA[j]);
                    accB[j] = ffma2(wv.y, xd, accB[j]);
                }
            }
        }
    }

    float acc[4][4];
#pragma unroll
    for (int j = 0; j < 4; j++) {
        unpack2(accA[j], acc[0][j], acc[1][j]);
        unpack2(accB[j], acc[2][j], acc[3][j]);
    }
#pragma unroll
    for (int oc = 0; oc < 4; oc++) {
        float4 tv = make_float4(acc[oc][0], acc[oc][1], acc[oc][2], acc[oc][3]);
        *(float4*)&g_t[(size_t)(b * 4 + oc) * L + l0 + tp] = tv;
    }
}

// ---------------------------------------------------------------------------
// Kernel 3: expand (4->40, 1x1) + sigmoid gate * y  -> motifact
// ---------------------------------------------------------------------------
__global__ __launch_bounds__(256)
void gate_kernel(const float* __restrict__ we, const float* __restrict__ be)
{
    __shared__ float sw[160];
    __shared__ float sb[40];
    const int tid = threadIdx.x;
    if (tid < 160) sw[tid] = we[tid];
    if (tid < 40)  sb[tid] = be[tid];
    __syncthreads();

    const int b = blockIdx.y;
    const int l = (blockIdx.x * 256 + tid) * 4;

    float4 tv[4];
#pragma unroll
    for (int rc = 0; rc < 4; rc++)
        tv[rc] = *(const float4*)&g_t[(size_t)(b * 4 + rc) * L + l];

    for (int oc = 0; oc < 40; oc++) {
        float w0 = sw[oc * 4 + 0], w1 = sw[oc * 4 + 1];
        float w2 = sw[oc * 4 + 2], w3 = sw[oc * 4 + 3];
        float bb = sb[oc];
        float4 g;
        g.x = bb + w0 * tv[0].x + w1 * tv[1].x + w2 * tv[2].x + w3 * tv[3].x;
        g.y = bb + w0 * tv[0].y + w1 * tv[1].y + w2 * tv[2].y + w3 * tv[3].y;
        g.z = bb + w0 * tv[0].z + w1 * tv[1].z + w2 * tv[2].z + w3 * tv[3].z;
        g.w = bb + w0 * tv[0].w + w1 * tv[1].w + w2 * tv[2].w + w3 * tv[3].w;
        g.x = 1.f / (1.f + __expf(-g.x));
        g.y = 1.f / (1.f + __expf(-g.y));
        g.z = 1.f / (1.f + __expf(-g.z));
        g.w = 1.f / (1.f + __expf(-g.w));
        size_t idx = (size_t)(b * 40 + oc) * L + l;
        float4 yv = *(const float4*)&g_y[idx];
        float4 mv = make_float4(g.x * yv.x, g.y * yv.y, g.z * yv.z, g.w * yv.w);
        *(float4*)&g_m[idx] = mv;
    }
}

// ---------------------------------------------------------------------------
// Kernel 4: effect conv (40->2, K=601, pad 300) + sigmoid + slice [500:-500]
//   f32x2: accumulators paired over adjacent output positions.
//   Weights pre-duplicated in smem: swt[cc][k] = {w0,w0,w1,w1} so one
//   ld.shared.v2.u64 yields both packed weight operands.
//   x window stored with +4-words-per-32 swizzle -> conflict-free LDS.128
//   at lane stride 8 floats.
// ---------------------------------------------------------------------------
#define T5   1024           // output positions per block
#define TH5  128
#define NP5  8              // positions per thread (consecutive)
#define K5P  608            // 601 padded to mult of 8
#define W5   1648           // T5 + K5P + 16
#define W5PS 1856           // swizzled physical stride: 1648 + 4*ceil(1648/32), padded
#define CH5  2              // channels per smem chunk

__device__ __forceinline__ int swz(int w) { return w + ((w >> 5) << 2); }

__global__ __launch_bounds__(TH5)
void effect_kernel(const float* __restrict__ w, const float* __restrict__ bias,
                   float* __restrict__ out)
{
    __shared__ __align__(16) float sm[CH5 * W5PS];      // swizzled m window
    __shared__ __align__(16) float swt[CH5 * K5P * 4];  // [cc][k][{w0,w0,w1,w1}]

    const int b   = blockIdx.y;
    const int lo0 = blockIdx.x * T5;        // offset in output coords
    const int g0  = lo0 + 200;              // = (500 + lo0) - 300, always >= 0
    const int tid = threadIdx.x;
    const int tp  = tid * NP5;

    // packed accumulators over position pairs: acc0[q] = ch0 @ (2q, 2q+1)
    u64 acc0[NP5 / 2], acc1[NP5 / 2];
    {
        u64 i0 = pack2(bias[0], bias[0]);
        u64 i1 = pack2(bias[1], bias[1]);
#pragma unroll
        for (int q = 0; q < NP5 / 2; q++) { acc0[q] = i0; acc1[q] = i1; }
    }

    for (int ch0 = 0; ch0 < 40; ch0 += CH5) {
        __syncthreads();   // protect previous chunk's smem until all done
        // weights, duplicated pairs
        for (int i = tid; i < CH5 * K5P; i += TH5) {
            int cc = i / K5P;
            int k  = i - cc * K5P;
            float w0v = 0.f, w1v = 0.f;
            if (k < 601) {
                w0v = w[((size_t)(0 * 40 + ch0 + cc)) * 601 + k];
                w1v = w[((size_t)(1 * 40 + ch0 + cc)) * 601 + k];
            }
            *(float4*)&swt[i * 4] = make_float4(w0v, w0v, w1v, w1v);
        }
        // x window, swizzled
        for (int i = tid; i < CH5 * W5; i += TH5) {
            int cc  = i / W5;
            int off = i - cc * W5;
            int g   = g0 + off;
            float v = (g < L) ? g_m[(size_t)(b * 40 + ch0 + cc) * L + g] : 0.f;
            sm[cc * W5PS + swz(off)] = v;
        }
        __syncthreads();

#pragma unroll 1
        for (int cc = 0; cc < CH5; cc++) {
            const float* xc = &sm[cc * W5PS];
            const float* wb = &swt[cc * (K5P * 4)];
#pragma unroll 1
            for (int k0 = 0; k0 < K5P; k0 += 8) {
                // load 16 window floats (offsets tp+k0 .. +15), swizzled addrs
                float xw[16];
#pragma unroll
                for (int q = 0; q < 4; q++) {
                    float4 v = *(const float4*)(xc + swz(tp + k0 + q * 4));
                    xw[q * 4 + 0] = v.x; xw[q * 4 + 1] = v.y;
                    xw[q * 4 + 2] = v.z; xw[q * 4 + 3] = v.w;
                }
                // build even / odd packed pairs once per 8-tap group
                u64 pe[8], po[7];
#pragma unroll
                for (int q = 0; q < 8; q++) pe[q] = pack2(xw[2 * q], xw[2 * q + 1]);
#pragma unroll
                for (int q = 0; q < 7; q++) po[q] = pack2(xw[2 * q + 1], xw[2 * q + 2]);

#pragma unroll
                for (int kk = 0; kk < 8; kk++) {
                    ulonglong2 wv = *(const ulonglong2*)(wb + (k0 + kk) * 4);
#pragma unroll
                    for (int q = 0; q < 4; q++) {
                        u64 xv = (kk & 1) ? po[((kk - 1) >> 1) + q]
                                          : pe[(kk >> 1) + q];
                        acc0[q] = ffma2(wv.x, xv, acc0[q]);
                        acc1[q] = ffma2(wv.y, xv, acc1[q]);
                    }
                }
            }
        }
    }

#pragma unroll
    for (int q = 0; q < NP5 / 2; q++) {
        float a0, a1, b0v, b1v;
        unpack2(acc0[q], a0, a1);
        unpack2(acc1[q], b0v, b1v);
        int lo = lo0 + tp + 2 * q;
        if (lo < LOUT)
            out[(size_t)(b * 2 + 0) * LOUT + lo] = 1.f / (1.f + __expf(-a0));
        if (lo + 1 < LOUT)
            out[(size_t)(b * 2 + 0) * LOUT + lo + 1] = 1.f / (1.f + __expf(-a1));
        if (lo < LOUT)
            out[(size_t)(b * 2 + 1) * LOUT + lo] = 1.f / (1.f + __expf(-b0v));
        if (lo + 1 < LOUT)
            out[(size_t)(b * 2 + 1) * LOUT + lo + 1] = 1.f / (1.f + __expf(-b1v));
    }
}

// ---------------------------------------------------------------------------
// Launch
// ---------------------------------------------------------------------------
extern "C" void kernel_launch(void* const* d_in, const int* in_sizes, int n_in,
                              void* d_out, int out_size)
{
    const float* x   = (const float*)d_in[0];
    const float* wm  = (const float*)d_in[1];
    const float* bm  = (const float*)d_in[2];
    const float* wr  = (const float*)d_in[3];
    const float* br  = (const float*)d_in[4];
    const float* wf  = (const float*)d_in[5];
    const float* bf  = (const float*)d_in[6];
    const float* wex = (const float*)d_in[7];
    const float* bex = (const float*)d_in[8];
    const float* wef = (const float*)d_in[9];
    const float* bef = (const float*)d_in[10];
    float* out = (float*)d_out;

    motif_kernel  <<<dim3(L / T1, B), TH1>>>(x, wm, bm, wr, br);
    fftconv_kernel<<<dim3(L / T3, B), TH3>>>(wf, bf);
    gate_kernel   <<<dim3(L / 1024, B), 256>>>(wex, bex);
    effect_kernel <<<dim3((LOUT + T5 - 1) / T5, B), TH5>>>(wef, bef, out);
}

// round 6
// speedup vs baseline: 1.3673x; 1.3673x over previous
#include <cuda_runtime.h>
#include <math.h>

// ---------------------------------------------------------------------------
// Shapes (fixed by the problem)
// ---------------------------------------------------------------------------
#define B    32
#define L    65536
#define LOUT 64536          // L - 1000 (slice [500:-500])

// Scratch (device globals; allocation in kernel_launch is forbidden)
__device__ float g_y[(size_t)B * 40 * L];   // motif output (post-softplus)
__device__ float g_s[(size_t)B * 4 * L];    // reduce output
__device__ float g_t[(size_t)B * 4 * L];    // fftconv output
__device__ float g_m[(size_t)B * 40 * L];   // motifact (gated)

// ---------------------------------------------------------------------------
// Kernel 1: motif conv (4->40, K=51, pad 25) + softplus + reduce (40->4, 1x1)
//   (R1 scalar version — proven)
// ---------------------------------------------------------------------------
#define T1   512            // output positions per block
#define TH1  128
#define K1P  52             // 51 padded to mult of 4 (pad taps have w=0)
#define XW1  564            // T1 + K1P + 4 rounding, mult of 4

__global__ __launch_bounds__(TH1)
void motif_kernel(const float* __restrict__ x,
                  const float* __restrict__ wm, const float* __restrict__ bm,
                  const float* __restrict__ wr, const float* __restrict__ br)
{
    __shared__ __align__(16) float swm[4 * K1P * 40];  // [c][k][oc], k padded
    __shared__ float swr[4 * 40];                      // [rc][oc]
    __shared__ float sbm[40];
    __shared__ float sbr[4];
    __shared__ __align__(16) float sx[4 * XW1];

    const int b   = blockIdx.y;
    const int l0  = blockIdx.x * T1;
    const int tid = threadIdx.x;

    // weights -> smem, transposed to [c][k][oc] with k zero-padded to 52
    for (int i = tid; i < 4 * K1P * 40; i += TH1) {
        int c  = i / (K1P * 40);
        int r  = i - c * (K1P * 40);
        int k  = r / 40;
        int oc = r - k * 40;
        swm[i] = (k < 51) ? wm[(oc * 4 + c) * 51 + k] : 0.f;
    }
    for (int i = tid; i < 160; i += TH1) swr[i] = wr[i];
    if (tid < 40) sbm[tid] = bm[tid];
    if (tid < 4)  sbr[tid] = br[tid];

    // x window [l0-25, l0-25+XW1)
    for (int i = tid; i < 4 * XW1; i += TH1) {
        int c   = i / XW1;
        int off = i - c * XW1;
        int g   = l0 - 25 + off;
        sx[i]   = (g >= 0 && g < L) ? x[(b * 4 + c) * L + g] : 0.f;
    }
    __syncthreads();

    const int tp = tid * 4;     // 4 consecutive output positions per thread

    float sacc[4][4];
#pragma unroll
    for (int rc = 0; rc < 4; rc++) {
        float bv = sbr[rc];
#pragma unroll
        for (int j = 0; j < 4; j++) sacc[rc][j] = bv;
    }

    for (int ocg = 0; ocg < 40; ocg += 8) {
        float acc[8][4];
#pragma unroll
        for (int o = 0; o < 8; o++) {
            float bv = sbm[ocg + o];
#pragma unroll
            for (int j = 0; j < 4; j++) acc[o][j] = bv;
        }

#pragma unroll
        for (int c = 0; c < 4; c++) {
            const float* xb = &sx[c * XW1 + tp];
            const float* wb = &swm[c * (K1P * 40) + ocg];
#pragma unroll 1
            for (int kg = 0; kg < K1P / 4; kg++) {
                const int k0 = kg * 4;
                float xq[8];
                float4 xa = *(const float4*)(xb + k0);
                float4 xc = *(const float4*)(xb + k0 + 4);
                xq[0]=xa.x; xq[1]=xa.y; xq[2]=xa.z; xq[3]=xa.w;
                xq[4]=xc.x; xq[5]=xc.y; xq[6]=xc.z; xq[7]=xc.w;
#pragma unroll
                for (int kk = 0; kk < 4; kk++) {
                    float4 wa = *(const float4*)(wb + (k0 + kk) * 40);
                    float4 wc = *(const float4*)(wb + (k0 + kk) * 40 + 4);
                    float wv[8] = {wa.x, wa.y, wa.z, wa.w, wc.x, wc.y, wc.z, wc.w};
#pragma unroll
                    for (int j = 0; j < 4; j++) {
                        float xv = xq[kk + j];
#pragma unroll
                        for (int o = 0; o < 8; o++)
                            acc[o][j] = fmaf(wv[o], xv, acc[o][j]);
                    }
                }
            }
        }

        // softplus, write y, accumulate reduce
#pragma unroll
        for (int o = 0; o < 8; o++) {
            const int oc = ocg + o;
            float4 yv;
            float* yp = (float*)&yv;
#pragma unroll
            for (int j = 0; j < 4; j++) {
                float v  = acc[o][j];
                float sp = fmaxf(v, 0.f) + __logf(1.f + __expf(-fabsf(v)));
                yp[j] = sp;
#pragma unroll
                for (int rc = 0; rc < 4; rc++)
                    sacc[rc][j] = fmaf(swr[rc * 40 + oc], sp, sacc[rc][j]);
            }
            *(float4*)&g_y[(size_t)(b * 40 + oc) * L + l0 + tp] = yv;
        }
    }

#pragma unroll
    for (int rc = 0; rc < 4; rc++) {
        float4 sv = make_float4(sacc[rc][0], sacc[rc][1], sacc[rc][2], sacc[rc][3]);
        *(float4*)&g_s[(size_t)(b * 4 + rc) * L + l0 + tp] = sv;
    }
}

// ---------------------------------------------------------------------------
// Kernel 2: fftconv (4->4, K=401, pad 200)   (R1 scalar version — proven)
// ---------------------------------------------------------------------------
#define T3   512
#define TH3  128
#define K3P  404            // 401 padded to mult of 4
#define XW3  920            // T3 + K3P + 4, mult of 4

__global__ __launch_bounds__(TH3)
void fftconv_kernel(const float* __restrict__ wf, const float* __restrict__ bf)
{
    __shared__ __align__(16) float sw[4 * K3P * 4];    // [c][k][oc]
    __shared__ float sb[4];
    __shared__ __align__(16) float ss[4 * XW3];

    const int b   = blockIdx.y;
    const int l0  = blockIdx.x * T3;
    const int tid = threadIdx.x;

    for (int i = tid; i < 4 * K3P * 4; i += TH3) {
        int c  = i / (K3P * 4);
        int r  = i - c * (K3P * 4);
        int k  = r / 4;
        int oc = r - k * 4;
        sw[i] = (k < 401) ? wf[(oc * 4 + c) * 401 + k] : 0.f;
    }
    if (tid < 4) sb[tid] = bf[tid];

    for (int i = tid; i < 4 * XW3; i += TH3) {
        int c   = i / XW3;
        int off = i - c * XW3;
        int g   = l0 - 200 + off;
        ss[i]   = (g >= 0 && g < L) ? g_s[(size_t)(b * 4 + c) * L + g] : 0.f;
    }
    __syncthreads();

    const int tp = tid * 4;
    float acc[4][4];
#pragma unroll
    for (int oc = 0; oc < 4; oc++) {
        float bv = sb[oc];
#pragma unroll
        for (int j = 0; j < 4; j++) acc[oc][j] = bv;
    }

#pragma unroll
    for (int c = 0; c < 4; c++) {
        const float* xb = &ss[c * XW3 + tp];
        const float* wb = &sw[c * (K3P * 4)];
#pragma unroll 1
        for (int kg = 0; kg < K3P / 4; kg++) {
            const int k0 = kg * 4;
            float xq[8];
            float4 xa = *(const float4*)(xb + k0);
            float4 xc = *(const float4*)(xb + k0 + 4);
            xq[0]=xa.x; xq[1]=xa.y; xq[2]=xa.z; xq[3]=xa.w;
            xq[4]=xc.x; xq[5]=xc.y; xq[6]=xc.z; xq[7]=xc.w;
#pragma unroll
            for (int kk = 0; kk < 4; kk++) {
                float4 wv = *(const float4*)(wb + (k0 + kk) * 4);
                float w0 = wv.x, w1 = wv.y, w2 = wv.z, w3 = wv.w;
#pragma unroll
                for (int j = 0; j < 4; j++) {
                    float xv = xq[kk + j];
                    acc[0][j] = fmaf(w0, xv, acc[0][j]);
                    acc[1][j] = fmaf(w1, xv, acc[1][j]);
                    acc[2][j] = fmaf(w2, xv, acc[2][j]);
                    acc[3][j] = fmaf(w3, xv, acc[3][j]);
                }
            }
        }
    }

#pragma unroll
    for (int oc = 0; oc < 4; oc++) {
        float4 tv = make_float4(acc[oc][0], acc[oc][1], acc[oc][2], acc[oc][3]);
        *(float4*)&g_t[(size_t)(b * 4 + oc) * L + l0 + tp] = tv;
    }
}

// ---------------------------------------------------------------------------
// Kernel 3: expand (4->40, 1x1) + sigmoid gate * y  -> motifact
// ---------------------------------------------------------------------------
__global__ __launch_bounds__(256)
void gate_kernel(const float* __restrict__ we, const float* __restrict__ be)
{
    __shared__ float sw[160];
    __shared__ float sb[40];
    const int tid = threadIdx.x;
    if (tid < 160) sw[tid] = we[tid];
    if (tid < 40)  sb[tid] = be[tid];
    __syncthreads();

    const int b = blockIdx.y;
    const int l = (blockIdx.x * 256 + tid) * 4;

    float4 tv[4];
#pragma unroll
    for (int rc = 0; rc < 4; rc++)
        tv[rc] = *(const float4*)&g_t[(size_t)(b * 4 + rc) * L + l];

    for (int oc = 0; oc < 40; oc++) {
        float w0 = sw[oc * 4 + 0], w1 = sw[oc * 4 + 1];
        float w2 = sw[oc * 4 + 2], w3 = sw[oc * 4 + 3];
        float bb = sb[oc];
        float4 g;
        g.x = bb + w0 * tv[0].x + w1 * tv[1].x + w2 * tv[2].x + w3 * tv[3].x;
        g.y = bb + w0 * tv[0].y + w1 * tv[1].y + w2 * tv[2].y + w3 * tv[3].y;
        g.z = bb + w0 * tv[0].z + w1 * tv[1].z + w2 * tv[2].z + w3 * tv[3].z;
        g.w = bb + w0 * tv[0].w + w1 * tv[1].w + w2 * tv[2].w + w3 * tv[3].w;
        g.x = 1.f / (1.f + __expf(-g.x));
        g.y = 1.f / (1.f + __expf(-g.y));
        g.z = 1.f / (1.f + __expf(-g.z));
        g.w = 1.f / (1.f + __expf(-g.w));
        size_t idx = (size_t)(b * 40 + oc) * L + l;
        float4 yv = *(const float4*)&g_y[idx];
        float4 mv = make_float4(g.x * yv.x, g.y * yv.y, g.z * yv.z, g.w * yv.w);
        *(float4*)&g_m[idx] = mv;
    }
}

// ---------------------------------------------------------------------------
// Kernel 4: effect conv (40->2, K=601, pad 300) + sigmoid + slice [500:-500]
//   Scalar FFMA. NP=16 positions/thread so FFMA fraction of issue slots ~96%.
//   Weights in smem [cc][k][2] -> uniform (broadcast) LDS.128 covering 4 taps.
//   x window swizzled (+4 floats per 32) -> conflict-free LDS.128 at lane
//   stride 16 floats.
// ---------------------------------------------------------------------------
#define T5   2048           // output positions per block
#define TH5  128
#define NP5  16             // positions per thread (consecutive)
#define K5P  608            // 601 padded to mult of 8
#define W5   2672           // T5 + K5P + 16
#define W5PS 3008           // swizzled physical stride: 2672 + 4*84
#define CH5  2              // channels per smem chunk

__device__ __forceinline__ int swz(int w) { return w + ((w >> 5) << 2); }

__global__ __launch_bounds__(TH5)
void effect_kernel(const float* __restrict__ w, const float* __restrict__ bias,
                   float* __restrict__ out)
{
    __shared__ __align__(16) float sm[CH5 * W5PS];      // swizzled m window
    __shared__ __align__(16) float swt[CH5 * K5P * 2];  // [cc][k][{w0,w1}]

    const int b   = blockIdx.y;
    const int lo0 = blockIdx.x * T5;        // offset in output coords
    const int g0  = lo0 + 200;              // = (500 + lo0) - 300, always >= 0
    const int tid = threadIdx.x;
    const int tp  = tid * NP5;

    float acc0[NP5], acc1[NP5];
    const float b0 = bias[0], b1 = bias[1];
#pragma unroll
    for (int j = 0; j < NP5; j++) { acc0[j] = b0; acc1[j] = b1; }

    for (int ch0 = 0; ch0 < 40; ch0 += CH5) {
        __syncthreads();   // protect previous chunk's smem until all done
        // weights: [cc][k][{w0,w1}], k zero-padded to K5P
        for (int i = tid; i < CH5 * K5P; i += TH5) {
            int cc = i / K5P;
            int k  = i - cc * K5P;
            float w0v = 0.f, w1v = 0.f;
            if (k < 601) {
                w0v = w[((size_t)(0 * 40 + ch0 + cc)) * 601 + k];
                w1v = w[((size_t)(1 * 40 + ch0 + cc)) * 601 + k];
            }
            *(float2*)&swt[i * 2] = make_float2(w0v, w1v);
        }
        // x window, swizzled
        for (int i = tid; i < CH5 * W5; i += TH5) {
            int cc  = i / W5;
            int off = i - cc * W5;
            int g   = g0 + off;
            float v = (g < L) ? g_m[(size_t)(b * 40 + ch0 + cc) * L + g] : 0.f;
            sm[cc * W5PS + swz(off)] = v;
        }
        __syncthreads();

#pragma unroll 1
        for (int cc = 0; cc < CH5; cc++) {
            const float* xc = &sm[cc * W5PS];
            const float* wb = &swt[cc * (K5P * 2)];
#pragma unroll 1
            for (int k0 = 0; k0 < K5P; k0 += 8) {
                // 24 window floats (offsets tp+k0 .. +23), swizzled addresses
                float xw[24];
#pragma unroll
                for (int q = 0; q < 6; q++) {
                    float4 v = *(const float4*)(xc + swz(tp + k0 + q * 4));
                    xw[q * 4 + 0] = v.x; xw[q * 4 + 1] = v.y;
                    xw[q * 4 + 2] = v.z; xw[q * 4 + 3] = v.w;
                }
                // 8 taps' weight pairs via 4 uniform LDS.128
                float wq[16];
#pragma unroll
                for (int q = 0; q < 4; q++) {
                    float4 v = *(const float4*)(wb + k0 * 2 + q * 4);
                    wq[q * 4 + 0] = v.x; wq[q * 4 + 1] = v.y;
                    wq[q * 4 + 2] = v.z; wq[q * 4 + 3] = v.w;
                }
#pragma unroll
                for (int kk = 0; kk < 8; kk++) {
                    float w0v = wq[2 * kk], w1v = wq[2 * kk + 1];
#pragma unroll
                    for (int j = 0; j < NP5; j++) {
                        float xv = xw[kk + j];
                        acc0[j] = fmaf(w0v, xv, acc0[j]);
                        acc1[j] = fmaf(w1v, xv, acc1[j]);
                    }
                }
            }
        }
    }

#pragma unroll
    for (int j = 0; j < NP5; j++) {
        int lo = lo0 + tp + j;
        if (lo < LOUT) {
            out[(size_t)(b * 2 + 0) * LOUT + lo] = 1.f / (1.f + __expf(-acc0[j]));
            out[(size_t)(b * 2 + 1) * LOUT + lo] = 1.f / (1.f + __expf(-acc1[j]));
        }
    }
}

// ---------------------------------------------------------------------------
// Launch
// ---------------------------------------------------------------------------
extern "C" void kernel_launch(void* const* d_in, const int* in_sizes, int n_in,
                              void* d_out, int out_size)
{
    const float* x   = (const float*)d_in[0];
    const float* wm  = (const float*)d_in[1];
    const float* bm  = (const float*)d_in[2];
    const float* wr  = (const float*)d_in[3];
    const float* br  = (const float*)d_in[4];
    const float* wf  = (const float*)d_in[5];
    const float* bf  = (const float*)d_in[6];
    const float* wex = (const float*)d_in[7];
    const float* bex = (const float*)d_in[8];
    const float* wef = (const float*)d_in[9];
    const float* bef = (const float*)d_in[10];
    float* out = (float*)d_out;

    motif_kernel  <<<dim3(L / T1, B), TH1>>>(x, wm, bm, wr, br);
    fftconv_kernel<<<dim3(L / T3, B), TH3>>>(wf, bf);
    gate_kernel   <<<dim3(L / 1024, B), 256>>>(wex, bex);
    effect_kernel <<<dim3((LOUT + T5 - 1) / T5, B), TH5>>>(wef, bef, out);
}

// round 7
// speedup vs baseline: 1.4758x; 1.0793x over previous
#include <cuda_runtime.h>
#include <math.h>

// ---------------------------------------------------------------------------
// Shapes (fixed by the problem)
// ---------------------------------------------------------------------------
#define B    32
#define L    65536
#define LOUT 64536          // L - 1000 (slice [500:-500])

// Scratch (device globals; allocation in kernel_launch is forbidden)
__device__ float g_y[(size_t)B * 40 * L];   // motif output (post-softplus)
__device__ float g_s[(size_t)B * 4 * L];    // reduce output
__device__ float g_t[(size_t)B * 4 * L];    // fftconv output
__device__ float g_m[(size_t)B * 40 * L];   // motifact (gated)

// ---------------------------------------------------------------------------
// Kernel 1: motif conv (4->40, K=51, pad 25) + softplus + reduce (40->4, 1x1)
//   (proven R1 scalar version — frozen)
// ---------------------------------------------------------------------------
#define T1   512            // output positions per block
#define TH1  128
#define K1P  52             // 51 padded to mult of 4 (pad taps have w=0)
#define XW1  564            // T1 + K1P + 4 rounding, mult of 4

__global__ __launch_bounds__(TH1)
void motif_kernel(const float* __restrict__ x,
                  const float* __restrict__ wm, const float* __restrict__ bm,
                  const float* __restrict__ wr, const float* __restrict__ br)
{
    __shared__ __align__(16) float swm[4 * K1P * 40];  // [c][k][oc], k padded
    __shared__ float swr[4 * 40];                      // [rc][oc]
    __shared__ float sbm[40];
    __shared__ float sbr[4];
    __shared__ __align__(16) float sx[4 * XW1];

    const int b   = blockIdx.y;
    const int l0  = blockIdx.x * T1;
    const int tid = threadIdx.x;

    // weights -> smem, transposed to [c][k][oc] with k zero-padded to 52
    for (int i = tid; i < 4 * K1P * 40; i += TH1) {
        int c  = i / (K1P * 40);
        int r  = i - c * (K1P * 40);
        int k  = r / 40;
        int oc = r - k * 40;
        swm[i] = (k < 51) ? wm[(oc * 4 + c) * 51 + k] : 0.f;
    }
    for (int i = tid; i < 160; i += TH1) swr[i] = wr[i];
    if (tid < 40) sbm[tid] = bm[tid];
    if (tid < 4)  sbr[tid] = br[tid];

    // x window [l0-25, l0-25+XW1)
    for (int i = tid; i < 4 * XW1; i += TH1) {
        int c   = i / XW1;
        int off = i - c * XW1;
        int g   = l0 - 25 + off;
        sx[i]   = (g >= 0 && g < L) ? x[(b * 4 + c) * L + g] : 0.f;
    }
    __syncthreads();

    const int tp = tid * 4;     // 4 consecutive output positions per thread

    float sacc[4][4];
#pragma unroll
    for (int rc = 0; rc < 4; rc++) {
        float bv = sbr[rc];
#pragma unroll
        for (int j = 0; j < 4; j++) sacc[rc][j] = bv;
    }

    for (int ocg = 0; ocg < 40; ocg += 8) {
        float acc[8][4];
#pragma unroll
        for (int o = 0; o < 8; o++) {
            float bv = sbm[ocg + o];
#pragma unroll
            for (int j = 0; j < 4; j++) acc[o][j] = bv;
        }

#pragma unroll
        for (int c = 0; c < 4; c++) {
            const float* xb = &sx[c * XW1 + tp];
            const float* wb = &swm[c * (K1P * 40) + ocg];
#pragma unroll 1
            for (int kg = 0; kg < K1P / 4; kg++) {
                const int k0 = kg * 4;
                float xq[8];
                float4 xa = *(const float4*)(xb + k0);
                float4 xc = *(const float4*)(xb + k0 + 4);
                xq[0]=xa.x; xq[1]=xa.y; xq[2]=xa.z; xq[3]=xa.w;
                xq[4]=xc.x; xq[5]=xc.y; xq[6]=xc.z; xq[7]=xc.w;
#pragma unroll
                for (int kk = 0; kk < 4; kk++) {
                    float4 wa = *(const float4*)(wb + (k0 + kk) * 40);
                    float4 wc = *(const float4*)(wb + (k0 + kk) * 40 + 4);
                    float wv[8] = {wa.x, wa.y, wa.z, wa.w, wc.x, wc.y, wc.z, wc.w};
#pragma unroll
                    for (int j = 0; j < 4; j++) {
                        float xv = xq[kk + j];
#pragma unroll
                        for (int o = 0; o < 8; o++)
                            acc[o][j] = fmaf(wv[o], xv, acc[o][j]);
                    }
                }
            }
        }

        // softplus, write y, accumulate reduce
#pragma unroll
        for (int o = 0; o < 8; o++) {
            const int oc = ocg + o;
            float4 yv;
            float* yp = (float*)&yv;
#pragma unroll
            for (int j = 0; j < 4; j++) {
                float v  = acc[o][j];
                float sp = fmaxf(v, 0.f) + __logf(1.f + __expf(-fabsf(v)));
                yp[j] = sp;
#pragma unroll
                for (int rc = 0; rc < 4; rc++)
                    sacc[rc][j] = fmaf(swr[rc * 40 + oc], sp, sacc[rc][j]);
            }
            *(float4*)&g_y[(size_t)(b * 40 + oc) * L + l0 + tp] = yv;
        }
    }

#pragma unroll
    for (int rc = 0; rc < 4; rc++) {
        float4 sv = make_float4(sacc[rc][0], sacc[rc][1], sacc[rc][2], sacc[rc][3]);
        *(float4*)&g_s[(size_t)(b * 4 + rc) * L + l0 + tp] = sv;
    }
}

// ---------------------------------------------------------------------------
// Kernel 2: fftconv (4->4, K=401, pad 200)   (proven R1 scalar — frozen)
// ---------------------------------------------------------------------------
#define T3   512
#define TH3  128
#define K3P  404            // 401 padded to mult of 4
#define XW3  920            // T3 + K3P + 4, mult of 4

__global__ __launch_bounds__(TH3)
void fftconv_kernel(const float* __restrict__ wf, const float* __restrict__ bf)
{
    __shared__ __align__(16) float sw[4 * K3P * 4];    // [c][k][oc]
    __shared__ float sb[4];
    __shared__ __align__(16) float ss[4 * XW3];

    const int b   = blockIdx.y;
    const int l0  = blockIdx.x * T3;
    const int tid = threadIdx.x;

    for (int i = tid; i < 4 * K3P * 4; i += TH3) {
        int c  = i / (K3P * 4);
        int r  = i - c * (K3P * 4);
        int k  = r / 4;
        int oc = r - k * 4;
        sw[i] = (k < 401) ? wf[(oc * 4 + c) * 401 + k] : 0.f;
    }
    if (tid < 4) sb[tid] = bf[tid];

    for (int i = tid; i < 4 * XW3; i += TH3) {
        int c   = i / XW3;
        int off = i - c * XW3;
        int g   = l0 - 200 + off;
        ss[i]   = (g >= 0 && g < L) ? g_s[(size_t)(b * 4 + c) * L + g] : 0.f;
    }
    __syncthreads();

    const int tp = tid * 4;
    float acc[4][4];
#pragma unroll
    for (int oc = 0; oc < 4; oc++) {
        float bv = sb[oc];
#pragma unroll
        for (int j = 0; j < 4; j++) acc[oc][j] = bv;
    }

#pragma unroll
    for (int c = 0; c < 4; c++) {
        const float* xb = &ss[c * XW3 + tp];
        const float* wb = &sw[c * (K3P * 4)];
#pragma unroll 1
        for (int kg = 0; kg < K3P / 4; kg++) {
            const int k0 = kg * 4;
            float xq[8];
            float4 xa = *(const float4*)(xb + k0);
            float4 xc = *(const float4*)(xb + k0 + 4);
            xq[0]=xa.x; xq[1]=xa.y; xq[2]=xa.z; xq[3]=xa.w;
            xq[4]=xc.x; xq[5]=xc.y; xq[6]=xc.z; xq[7]=xc.w;
#pragma unroll
            for (int kk = 0; kk < 4; kk++) {
                float4 wv = *(const float4*)(wb + (k0 + kk) * 4);
                float w0 = wv.x, w1 = wv.y, w2 = wv.z, w3 = wv.w;
#pragma unroll
                for (int j = 0; j < 4; j++) {
                    float xv = xq[kk + j];
                    acc[0][j] = fmaf(w0, xv, acc[0][j]);
                    acc[1][j] = fmaf(w1, xv, acc[1][j]);
                    acc[2][j] = fmaf(w2, xv, acc[2][j]);
                    acc[3][j] = fmaf(w3, xv, acc[3][j]);
                }
            }
        }
    }

#pragma unroll
    for (int oc = 0; oc < 4; oc++) {
        float4 tv = make_float4(acc[oc][0], acc[oc][1], acc[oc][2], acc[oc][3]);
        *(float4*)&g_t[(size_t)(b * 4 + oc) * L + l0 + tp] = tv;
    }
}

// ---------------------------------------------------------------------------
// Kernel 3: expand (4->40, 1x1) + sigmoid gate * y  -> motifact  (frozen)
// ---------------------------------------------------------------------------
__global__ __launch_bounds__(256)
void gate_kernel(const float* __restrict__ we, const float* __restrict__ be)
{
    __shared__ float sw[160];
    __shared__ float sb[40];
    const int tid = threadIdx.x;
    if (tid < 160) sw[tid] = we[tid];
    if (tid < 40)  sb[tid] = be[tid];
    __syncthreads();

    const int b = blockIdx.y;
    const int l = (blockIdx.x * 256 + tid) * 4;

    float4 tv[4];
#pragma unroll
    for (int rc = 0; rc < 4; rc++)
        tv[rc] = *(const float4*)&g_t[(size_t)(b * 4 + rc) * L + l];

    for (int oc = 0; oc < 40; oc++) {
        float w0 = sw[oc * 4 + 0], w1 = sw[oc * 4 + 1];
        float w2 = sw[oc * 4 + 2], w3 = sw[oc * 4 + 3];
        float bb = sb[oc];
        float4 g;
        g.x = bb + w0 * tv[0].x + w1 * tv[1].x + w2 * tv[2].x + w3 * tv[3].x;
        g.y = bb + w0 * tv[0].y + w1 * tv[1].y + w2 * tv[2].y + w3 * tv[3].y;
        g.z = bb + w0 * tv[0].z + w1 * tv[1].z + w2 * tv[2].z + w3 * tv[3].z;
        g.w = bb + w0 * tv[0].w + w1 * tv[1].w + w2 * tv[2].w + w3 * tv[3].w;
        g.x = 1.f / (1.f + __expf(-g.x));
        g.y = 1.f / (1.f + __expf(-g.y));
        g.z = 1.f / (1.f + __expf(-g.z));
        g.w = 1.f / (1.f + __expf(-g.w));
        size_t idx = (size_t)(b * 40 + oc) * L + l;
        float4 yv = *(const float4*)&g_y[idx];
        float4 mv = make_float4(g.x * yv.x, g.y * yv.y, g.z * yv.z, g.w * yv.w);
        *(float4*)&g_m[idx] = mv;
    }
}

// ---------------------------------------------------------------------------
// Kernel 4: effect conv (40->2, K=601, pad 300) + sigmoid + slice [500:-500]
//   Period-16 swizzle: phys(w) = w + 4*(w/16). Thread window base tp = tid*16
//   is 16-aligned, so its physical base is xc + tid*20, advancing by exactly
//   20 floats per 16-tap macro-iteration -> ALL inner LDS at immediate
//   offsets {0,4,8,12,20,24,28,32}; near-zero address ALU.
//   Conflict-free: 8-lane phase, dphys = 20 floats -> banks {0,20,8,28,...}.
//   Per macro-iter: 512 FFMA + 8 x-LDS.128 + 8 w-LDS.128 (broadcast).
// ---------------------------------------------------------------------------
#define T5    2048          // output positions per block
#define TH5   128
#define NP5   16            // positions per thread (consecutive)
#define K5P   608           // 601 padded to mult of 16
#define W5    2672          // logical window: T5 + K5P + 16
#define W5PS  3344          // physical: 2672 + 4*(2672/16) = 3340, pad to mult16
#define CH5   2             // channels per smem chunk

__device__ __forceinline__ int swz16(int w) { return w + ((w >> 4) << 2); }

__global__ __launch_bounds__(TH5)
void effect_kernel(const float* __restrict__ w, const float* __restrict__ bias,
                   float* __restrict__ out)
{
    __shared__ __align__(16) float sm[CH5 * W5PS];      // swizzled m window
    __shared__ __align__(16) float swt[CH5 * K5P * 2];  // [cc][k][{w0,w1}]

    const int b   = blockIdx.y;
    const int lo0 = blockIdx.x * T5;        // offset in output coords
    const int g0  = lo0 + 200;              // = (500 + lo0) - 300, always >= 0
    const int tid = threadIdx.x;
    const int tp  = tid * NP5;              // 16-aligned logical base

    float acc0[NP5], acc1[NP5];
    const float b0 = bias[0], b1 = bias[1];
#pragma unroll
    for (int j = 0; j < NP5; j++) { acc0[j] = b0; acc1[j] = b1; }

    for (int ch0 = 0; ch0 < 40; ch0 += CH5) {
        __syncthreads();   // protect previous chunk's smem until all done
        // weights: [cc][k][{w0,w1}], k zero-padded to K5P
        for (int i = tid; i < CH5 * K5P; i += TH5) {
            int cc = i / K5P;
            int k  = i - cc * K5P;
            float w0v = 0.f, w1v = 0.f;
            if (k < 601) {
                w0v = w[((size_t)(0 * 40 + ch0 + cc)) * 601 + k];
                w1v = w[((size_t)(1 * 40 + ch0 + cc)) * 601 + k];
            }
            *(float2*)&swt[i * 2] = make_float2(w0v, w1v);
        }
        // x window, period-16 swizzled
        for (int i = tid; i < CH5 * W5; i += TH5) {
            int cc  = i / W5;
            int off = i - cc * W5;
            int g   = g0 + off;
            float v = (g < L) ? g_m[(size_t)(b * 40 + ch0 + cc) * L + g] : 0.f;
            sm[cc * W5PS + swz16(off)] = v;
        }
        __syncthreads();

#pragma unroll 1
        for (int cc = 0; cc < CH5; cc++) {
            // physical base for this thread's window start (tp is 16-aligned:
            // phys(tp) = tp*20/16 = tid*20); advances by 20 per 16 taps.
            const float* pb = &sm[cc * W5PS] + tid * 20;
            const float* wb = &swt[cc * (K5P * 2)];
#pragma unroll 1
            for (int k0 = 0; k0 < K5P; k0 += 16) {
                // 32 logical window floats at immediate physical offsets
                float xw[32];
                {
                    float4 v0 = *(const float4*)(pb + 0);
                    float4 v1 = *(const float4*)(pb + 4);
                    float4 v2 = *(const float4*)(pb + 8);
                    float4 v3 = *(const float4*)(pb + 12);
                    float4 v4 = *(const float4*)(pb + 20);
                    float4 v5 = *(const float4*)(pb + 24);
                    float4 v6 = *(const float4*)(pb + 28);
                    float4 v7 = *(const float4*)(pb + 32);
                    xw[0]=v0.x;  xw[1]=v0.y;  xw[2]=v0.z;  xw[3]=v0.w;
                    xw[4]=v1.x;  xw[5]=v1.y;  xw[6]=v1.z;  xw[7]=v1.w;
                    xw[8]=v2.x;  xw[9]=v2.y;  xw[10]=v2.z; xw[11]=v2.w;
                    xw[12]=v3.x; xw[13]=v3.y; xw[14]=v3.z; xw[15]=v3.w;
                    xw[16]=v4.x; xw[17]=v4.y; xw[18]=v4.z; xw[19]=v4.w;
                    xw[20]=v5.x; xw[21]=v5.y; xw[22]=v5.z; xw[23]=v5.w;
                    xw[24]=v6.x; xw[25]=v6.y; xw[26]=v6.z; xw[27]=v6.w;
                    xw[28]=v7.x; xw[29]=v7.y; xw[30]=v7.z; xw[31]=v7.w;
                }
                // taps k0 .. k0+7
                {
                    float wq[16];
#pragma unroll
                    for (int q = 0; q < 4; q++) {
                        float4 v = *(const float4*)(wb + k0 * 2 + q * 4);
                        wq[q * 4 + 0] = v.x; wq[q * 4 + 1] = v.y;
                        wq[q * 4 + 2] = v.z; wq[q * 4 + 3] = v.w;
                    }
#pragma unroll
                    for (int kk = 0; kk < 8; kk++) {
                        float w0v = wq[2 * kk], w1v = wq[2 * kk + 1];
#pragma unroll
                        for (int j = 0; j < NP5; j++) {
                            float xv = xw[kk + j];
                            acc0[j] = fmaf(w0v, xv, acc0[j]);
                            acc1[j] = fmaf(w1v, xv, acc1[j]);
                        }
                    }
                }
                // taps k0+8 .. k0+15
                {
                    float wq[16];
#pragma unroll
                    for (int q = 0; q < 4; q++) {
                        float4 v = *(const float4*)(wb + k0 * 2 + 16 + q * 4);
                        wq[q * 4 + 0] = v.x; wq[q * 4 + 1] = v.y;
                        wq[q * 4 + 2] = v.z; wq[q * 4 + 3] = v.w;
                    }
#pragma unroll
                    for (int kk = 0; kk < 8; kk++) {
                        float w0v = wq[2 * kk], w1v = wq[2 * kk + 1];
#pragma unroll
                        for (int j = 0; j < NP5; j++) {
                            float xv = xw[8 + kk + j];
                            acc0[j] = fmaf(w0v, xv, acc0[j]);
                            acc1[j] = fmaf(w1v, xv, acc1[j]);
                        }
                    }
                }
                pb += 20;   // phys advance for 16 logical floats
            }
        }
    }

#pragma unroll
    for (int j = 0; j < NP5; j++) {
        int lo = lo0 + tp + j;
        if (lo < LOUT) {
            out[(size_t)(b * 2 + 0) * LOUT + lo] = 1.f / (1.f + __expf(-acc0[j]));
            out[(size_t)(b * 2 + 1) * LOUT + lo] = 1.f / (1.f + __expf(-acc1[j]));
        }
    }
}

// ---------------------------------------------------------------------------
// Launch
// ---------------------------------------------------------------------------
extern "C" void kernel_launch(void* const* d_in, const int* in_sizes, int n_in,
                              void* d_out, int out_size)
{
    const float* x   = (const float*)d_in[0];
    const float* wm  = (const float*)d_in[1];
    const float* bm  = (const float*)d_in[2];
    const float* wr  = (const float*)d_in[3];
    const float* br  = (const float*)d_in[4];
    const float* wf  = (const float*)d_in[5];
    const float* bf  = (const float*)d_in[6];
    const float* wex = (const float*)d_in[7];
    const float* bex = (const float*)d_in[8];
    const float* wef = (const float*)d_in[9];
    const float* bef = (const float*)d_in[10];
    float* out = (float*)d_out;

    motif_kernel  <<<dim3(L / T1, B), TH1>>>(x, wm, bm, wr, br);
    fftconv_kernel<<<dim3(L / T3, B), TH3>>>(wf, bf);
    gate_kernel   <<<dim3(L / 1024, B), 256>>>(wex, bex);
    effect_kernel <<<dim3((LOUT + T5 - 1) / T5, B), TH5>>>(wef, bef, out);
}

// round 8
// speedup vs baseline: 2.4699x; 1.6736x over previous
#include <cuda_runtime.h>
#include <math.h>
#include <stdint.h>

// ---------------------------------------------------------------------------
// Shapes (fixed by the problem)
// ---------------------------------------------------------------------------
#define B    32
#define L    65536
#define LOUT 64536          // L - 1000 (slice [500:-500])

// Scratch (device globals; allocation in kernel_launch is forbidden)
__device__ float g_y[(size_t)B * 40 * L];   // motif output (post-softplus)
__device__ float g_s[(size_t)B * 4 * L];    // reduce output
__device__ float g_t[(size_t)B * 4 * L];    // fftconv output
__device__ float g_m[(size_t)B * 40 * L];   // motifact (gated)

// ---------------------------------------------------------------------------
// Kernel 1: motif conv (4->40, K=51, pad 25) + softplus + reduce (40->4, 1x1)
//   (proven scalar version — frozen)
// ---------------------------------------------------------------------------
#define T1   512
#define TH1  128
#define K1P  52
#define XW1  564

__global__ __launch_bounds__(TH1)
void motif_kernel(const float* __restrict__ x,
                  const float* __restrict__ wm, const float* __restrict__ bm,
                  const float* __restrict__ wr, const float* __restrict__ br)
{
    __shared__ __align__(16) float swm[4 * K1P * 40];
    __shared__ float swr[4 * 40];
    __shared__ float sbm[40];
    __shared__ float sbr[4];
    __shared__ __align__(16) float sx[4 * XW1];

    const int b   = blockIdx.y;
    const int l0  = blockIdx.x * T1;
    const int tid = threadIdx.x;

    for (int i = tid; i < 4 * K1P * 40; i += TH1) {
        int c  = i / (K1P * 40);
        int r  = i - c * (K1P * 40);
        int k  = r / 40;
        int oc = r - k * 40;
        swm[i] = (k < 51) ? wm[(oc * 4 + c) * 51 + k] : 0.f;
    }
    for (int i = tid; i < 160; i += TH1) swr[i] = wr[i];
    if (tid < 40) sbm[tid] = bm[tid];
    if (tid < 4)  sbr[tid] = br[tid];

    for (int i = tid; i < 4 * XW1; i += TH1) {
        int c   = i / XW1;
        int off = i - c * XW1;
        int g   = l0 - 25 + off;
        sx[i]   = (g >= 0 && g < L) ? x[(b * 4 + c) * L + g] : 0.f;
    }
    __syncthreads();

    const int tp = tid * 4;

    float sacc[4][4];
#pragma unroll
    for (int rc = 0; rc < 4; rc++) {
        float bv = sbr[rc];
#pragma unroll
        for (int j = 0; j < 4; j++) sacc[rc][j] = bv;
    }

    for (int ocg = 0; ocg < 40; ocg += 8) {
        float acc[8][4];
#pragma unroll
        for (int o = 0; o < 8; o++) {
            float bv = sbm[ocg + o];
#pragma unroll
            for (int j = 0; j < 4; j++) acc[o][j] = bv;
        }

#pragma unroll
        for (int c = 0; c < 4; c++) {
            const float* xb = &sx[c * XW1 + tp];
            const float* wb = &swm[c * (K1P * 40) + ocg];
#pragma unroll 1
            for (int kg = 0; kg < K1P / 4; kg++) {
                const int k0 = kg * 4;
                float xq[8];
                float4 xa = *(const float4*)(xb + k0);
                float4 xc = *(const float4*)(xb + k0 + 4);
                xq[0]=xa.x; xq[1]=xa.y; xq[2]=xa.z; xq[3]=xa.w;
                xq[4]=xc.x; xq[5]=xc.y; xq[6]=xc.z; xq[7]=xc.w;
#pragma unroll
                for (int kk = 0; kk < 4; kk++) {
                    float4 wa = *(const float4*)(wb + (k0 + kk) * 40);
                    float4 wc = *(const float4*)(wb + (k0 + kk) * 40 + 4);
                    float wv[8] = {wa.x, wa.y, wa.z, wa.w, wc.x, wc.y, wc.z, wc.w};
#pragma unroll
                    for (int j = 0; j < 4; j++) {
                        float xv = xq[kk + j];
#pragma unroll
                        for (int o = 0; o < 8; o++)
                            acc[o][j] = fmaf(wv[o], xv, acc[o][j]);
                    }
                }
            }
        }

#pragma unroll
        for (int o = 0; o < 8; o++) {
            const int oc = ocg + o;
            float4 yv;
            float* yp = (float*)&yv;
#pragma unroll
            for (int j = 0; j < 4; j++) {
                float v  = acc[o][j];
                float sp = fmaxf(v, 0.f) + __logf(1.f + __expf(-fabsf(v)));
                yp[j] = sp;
#pragma unroll
                for (int rc = 0; rc < 4; rc++)
                    sacc[rc][j] = fmaf(swr[rc * 40 + oc], sp, sacc[rc][j]);
            }
            *(float4*)&g_y[(size_t)(b * 40 + oc) * L + l0 + tp] = yv;
        }
    }

#pragma unroll
    for (int rc = 0; rc < 4; rc++) {
        float4 sv = make_float4(sacc[rc][0], sacc[rc][1], sacc[rc][2], sacc[rc][3]);
        *(float4*)&g_s[(size_t)(b * 4 + rc) * L + l0 + tp] = sv;
    }
}

// ---------------------------------------------------------------------------
// Kernel 2: fftconv (4->4, K=401, pad 200)   (frozen)
// ---------------------------------------------------------------------------
#define T3   512
#define TH3  128
#define K3P  404
#define XW3  920

__global__ __launch_bounds__(TH3)
void fftconv_kernel(const float* __restrict__ wf, const float* __restrict__ bf)
{
    __shared__ __align__(16) float sw[4 * K3P * 4];
    __shared__ float sb[4];
    __shared__ __align__(16) float ss[4 * XW3];

    const int b   = blockIdx.y;
    const int l0  = blockIdx.x * T3;
    const int tid = threadIdx.x;

    for (int i = tid; i < 4 * K3P * 4; i += TH3) {
        int c  = i / (K3P * 4);
        int r  = i - c * (K3P * 4);
        int k  = r / 4;
        int oc = r - k * 4;
        sw[i] = (k < 401) ? wf[(oc * 4 + c) * 401 + k] : 0.f;
    }
    if (tid < 4) sb[tid] = bf[tid];

    for (int i = tid; i < 4 * XW3; i += TH3) {
        int c   = i / XW3;
        int off = i - c * XW3;
        int g   = l0 - 200 + off;
        ss[i]   = (g >= 0 && g < L) ? g_s[(size_t)(b * 4 + c) * L + g] : 0.f;
    }
    __syncthreads();

    const int tp = tid * 4;
    float acc[4][4];
#pragma unroll
    for (int oc = 0; oc < 4; oc++) {
        float bv = sb[oc];
#pragma unroll
        for (int j = 0; j < 4; j++) acc[oc][j] = bv;
    }

#pragma unroll
    for (int c = 0; c < 4; c++) {
        const float* xb = &ss[c * XW3 + tp];
        const float* wb = &sw[c * (K3P * 4)];
#pragma unroll 1
        for (int kg = 0; kg < K3P / 4; kg++) {
            const int k0 = kg * 4;
            float xq[8];
            float4 xa = *(const float4*)(xb + k0);
            float4 xc = *(const float4*)(xb + k0 + 4);
            xq[0]=xa.x; xq[1]=xa.y; xq[2]=xa.z; xq[3]=xa.w;
            xq[4]=xc.x; xq[5]=xc.y; xq[6]=xc.z; xq[7]=xc.w;
#pragma unroll
            for (int kk = 0; kk < 4; kk++) {
                float4 wv = *(const float4*)(wb + (k0 + kk) * 4);
                float w0 = wv.x, w1 = wv.y, w2 = wv.z, w3 = wv.w;
#pragma unroll
                for (int j = 0; j < 4; j++) {
                    float xv = xq[kk + j];
                    acc[0][j] = fmaf(w0, xv, acc[0][j]);
                    acc[1][j] = fmaf(w1, xv, acc[1][j]);
                    acc[2][j] = fmaf(w2, xv, acc[2][j]);
                    acc[3][j] = fmaf(w3, xv, acc[3][j]);
                }
            }
        }
    }

#pragma unroll
    for (int oc = 0; oc < 4; oc++) {
        float4 tv = make_float4(acc[oc][0], acc[oc][1], acc[oc][2], acc[oc][3]);
        *(float4*)&g_t[(size_t)(b * 4 + oc) * L + l0 + tp] = tv;
    }
}

// ---------------------------------------------------------------------------
// Kernel 3: expand (4->40, 1x1) + sigmoid gate * y  -> motifact  (frozen)
// ---------------------------------------------------------------------------
__global__ __launch_bounds__(256)
void gate_kernel(const float* __restrict__ we, const float* __restrict__ be)
{
    __shared__ float sw[160];
    __shared__ float sb[40];
    const int tid = threadIdx.x;
    if (tid < 160) sw[tid] = we[tid];
    if (tid < 40)  sb[tid] = be[tid];
    __syncthreads();

    const int b = blockIdx.y;
    const int l = (blockIdx.x * 256 + tid) * 4;

    float4 tv[4];
#pragma unroll
    for (int rc = 0; rc < 4; rc++)
        tv[rc] = *(const float4*)&g_t[(size_t)(b * 4 + rc) * L + l];

    for (int oc = 0; oc < 40; oc++) {
        float w0 = sw[oc * 4 + 0], w1 = sw[oc * 4 + 1];
        float w2 = sw[oc * 4 + 2], w3 = sw[oc * 4 + 3];
        float bb = sb[oc];
        float4 g;
        g.x = bb + w0 * tv[0].x + w1 * tv[1].x + w2 * tv[2].x + w3 * tv[3].x;
        g.y = bb + w0 * tv[0].y + w1 * tv[1].y + w2 * tv[2].y + w3 * tv[3].y;
        g.z = bb + w0 * tv[0].z + w1 * tv[1].z + w2 * tv[2].z + w3 * tv[3].z;
        g.w = bb + w0 * tv[0].w + w1 * tv[1].w + w2 * tv[2].w + w3 * tv[3].w;
        g.x = 1.f / (1.f + __expf(-g.x));
        g.y = 1.f / (1.f + __expf(-g.y));
        g.z = 1.f / (1.f + __expf(-g.z));
        g.w = 1.f / (1.f + __expf(-g.w));
        size_t idx = (size_t)(b * 40 + oc) * L + l;
        float4 yv = *(const float4*)&g_y[idx];
        float4 mv = make_float4(g.x * yv.x, g.y * yv.y, g.z * yv.z, g.w * yv.w);
        *(float4*)&g_m[idx] = mv;
    }
}

// ---------------------------------------------------------------------------
// Kernel 4: effect conv (40->2, K=601) via tf32 mma.sync (FIR-as-GEMM)
//
//   out[LO + 8m + n] = bias + sum_c sum_j w[oc,c,j-8m] * xm[c, LO+200+n+j]
//   A[m][j] = w[j-8m]  (banded, zero-padded)  -- 16x8 tf32 fragment
//   B[j][n] = xm[LO+200+J0+j+n]               -- Toeplitz, 8x8 tf32 fragment
//   j in [0, 728), 91 chunks of 8. Both M and N fully utilized.
//
//   CTA: 128 threads = 4 warps, 2048 positions (512/warp = 4 MMA tiles).
//   Operands pre-converted to tf32 (cvt.rna) at smem-store time.
// ---------------------------------------------------------------------------
#define ET_POS   2048       // positions per CTA
#define ET_TH    128
#define ET_WLEN  2656       // smem window per channel: (2048-128)+734 pad to /32
#define ET_WPAD  864        // padded weight array per (oc, cc): 128 + 601 + pad
#define ET_CH    2          // channels per chunk
#define ET_NJ    728        // extended j range (91 chunks of 8)

__device__ __forceinline__ uint32_t f2tf(float v) {
    uint32_t r;
    asm("cvt.rna.tf32.f32 %0, %1;" : "=r"(r) : "f"(v));
    return r;
}

__device__ __forceinline__ void mma_tf32(float& d0, float& d1, float& d2, float& d3,
                                         uint32_t a0, uint32_t a1, uint32_t a2, uint32_t a3,
                                         uint32_t b0, uint32_t b1) {
    asm volatile(
        "mma.sync.aligned.m16n8k8.row.col.f32.tf32.tf32.f32 "
        "{%0,%1,%2,%3}, {%4,%5,%6,%7}, {%8,%9}, {%0,%1,%2,%3};\n"
        : "+f"(d0), "+f"(d1), "+f"(d2), "+f"(d3)
        : "r"(a0), "r"(a1), "r"(a2), "r"(a3), "r"(b0), "r"(b1));
}

__global__ __launch_bounds__(ET_TH)
void effect_kernel(const float* __restrict__ w, const float* __restrict__ bias,
                   float* __restrict__ out)
{
    __shared__ uint32_t sm_x[ET_CH * ET_WLEN];     // tf32 bits of x window
    __shared__ uint32_t sm_w[2 * ET_CH * ET_WPAD]; // tf32 bits, [oc][cc][WPAD]

    const int b    = blockIdx.y;
    const int LOc  = blockIdx.x * ET_POS;          // CTA base in output coords
    const int tid  = threadIdx.x;
    const int wid  = tid >> 5;
    const int lane = tid & 31;
    const int grp  = lane >> 2;                    // groupID (0..7)
    const int tig  = lane & 3;                     // threadID_in_group (0..3)
    const int wrel = wid * 512;                    // warp base rel CTA

    // accumulators: 4 tiles x 2 outch x 4 frag regs
    float acc[4][2][4];
    const float b0v = bias[0], b1v = bias[1];
#pragma unroll
    for (int t = 0; t < 4; t++)
#pragma unroll
        for (int r = 0; r < 4; r++) { acc[t][0][r] = b0v; acc[t][1][r] = b1v; }

    for (int ch0 = 0; ch0 < 40; ch0 += ET_CH) {
        __syncthreads();   // protect previous chunk
        // weights: zero-fill then place 601 taps at offset 128, tf32-converted
        for (int i = tid; i < 2 * ET_CH * ET_WPAD; i += ET_TH) sm_w[i] = 0u;
        __syncthreads();
        for (int i = tid; i < 2 * ET_CH * 601; i += ET_TH) {
            int oc = i / (ET_CH * 601);
            int r  = i - oc * (ET_CH * 601);
            int cc = r / 601;
            int k  = r - cc * 601;
            sm_w[(oc * ET_CH + cc) * ET_WPAD + 128 + k] =
                f2tf(w[((size_t)(oc * 40 + ch0 + cc)) * 601 + k]);
        }
        // x window: input idx = LOc + 200 + off, tf32-converted
        for (int i = tid; i < ET_CH * ET_WLEN; i += ET_TH) {
            int cc  = i / ET_WLEN;
            int off = i - cc * ET_WLEN;
            int g   = LOc + 200 + off;
            float v = (g < L) ? g_m[(size_t)(b * 40 + ch0 + cc) * L + g] : 0.f;
            sm_x[i] = f2tf(v);
        }
        __syncthreads();

#pragma unroll 1
        for (int cc = 0; cc < ET_CH; cc++) {
            const uint32_t* xw  = &sm_x[cc * ET_WLEN + wrel];
            const uint32_t* w0p = &sm_w[(0 * ET_CH + cc) * ET_WPAD];
            const uint32_t* w1p = &sm_w[(1 * ET_CH + cc) * ET_WPAD];
            int ai = 128 + tig - 8 * grp;   // + J0 each step
            int bi = grp + tig;             // + J0 (+ t*128) each step
#pragma unroll 1
            for (int J0 = 0; J0 < ET_NJ; J0 += 8) {
                uint32_t a00 = w0p[ai],     a01 = w0p[ai - 64];
                uint32_t a02 = w0p[ai + 4], a03 = w0p[ai - 60];
                uint32_t a10 = w1p[ai],     a11 = w1p[ai - 64];
                uint32_t a12 = w1p[ai + 4], a13 = w1p[ai - 60];
#pragma unroll
                for (int t = 0; t < 4; t++) {
                    uint32_t bb0 = xw[bi + t * 128];
                    uint32_t bb1 = xw[bi + t * 128 + 4];
                    mma_tf32(acc[t][0][0], acc[t][0][1], acc[t][0][2], acc[t][0][3],
                             a00, a01, a02, a03, bb0, bb1);
                    mma_tf32(acc[t][1][0], acc[t][1][1], acc[t][1][2], acc[t][1][3],
                             a10, a11, a12, a13, bb0, bb1);
                }
                ai += 8; bi += 8;
            }
        }
    }

    // epilogue: sigmoid + store (C frag: c0:(g,2t) c1:(g,2t+1) c2:(g+8,2t) c3:(g+8,2t+1))
#pragma unroll
    for (int t = 0; t < 4; t++) {
        int base = LOc + wrel + t * 128;
        int p0   = base + 8 * grp + 2 * tig;       // c0/c1
        int p2   = p0 + 64;                        // c2/c3
#pragma unroll
        for (int oc = 0; oc < 2; oc++) {
            float* op = out + (size_t)(b * 2 + oc) * LOUT;
            float s0 = 1.f / (1.f + __expf(-acc[t][oc][0]));
            float s1 = 1.f / (1.f + __expf(-acc[t][oc][1]));
            float s2 = 1.f / (1.f + __expf(-acc[t][oc][2]));
            float s3 = 1.f / (1.f + __expf(-acc[t][oc][3]));
            if (p0 < LOUT)     op[p0]     = s0;
            if (p0 + 1 < LOUT) op[p0 + 1] = s1;
            if (p2 < LOUT)     op[p2]     = s2;
            if (p2 + 1 < LOUT) op[p2 + 1] = s3;
        }
    }
}

// ---------------------------------------------------------------------------
// Launch
// ---------------------------------------------------------------------------
extern "C" void kernel_launch(void* const* d_in, const int* in_sizes, int n_in,
                              void* d_out, int out_size)
{
    const float* x   = (const float*)d_in[0];
    const float* wm  = (const float*)d_in[1];
    const float* bm  = (const float*)d_in[2];
    const float* wr  = (const float*)d_in[3];
    const float* br  = (const float*)d_in[4];
    const float* wf  = (const float*)d_in[5];
    const float* bf  = (const float*)d_in[6];
    const float* wex = (const float*)d_in[7];
    const float* bex = (const float*)d_in[8];
    const float* wef = (const float*)d_in[9];
    const float* bef = (const float*)d_in[10];
    float* out = (float*)d_out;

    motif_kernel  <<<dim3(L / T1, B), TH1>>>(x, wm, bm, wr, br);
    fftconv_kernel<<<dim3(L / T3, B), TH3>>>(wf, bf);
    gate_kernel   <<<dim3(L / 1024, B), 256>>>(wex, bex);
    effect_kernel <<<dim3((LOUT + ET_POS - 1) / ET_POS, B), ET_TH>>>(wef, bef, out);
}